// round 15
// baseline (speedup 1.0000x reference)
#include <cuda_runtime.h>
#include <cuda_fp16.h>
#include <cstdint>
#include <cstddef>

// out[b,s,d] = 16*sum_v x[b,s,v]*emb[v,d] + pos[s,d]*any(x[b,s,:])
// GEMM M=8192, N=256, K=8192. fp16 table = fp16(emb*16), x exact in fp16,
// fp32 accumulate. Baseline PTX path (compute_103: no tcgen05).
// R15 = R9 loop verbatim, but split-N: CTA 64x128, 8 warps (2Mx4N, warp
// 32x32), 256 thr, ~95 regs, 97KB smem -> 2 CTAs/SM co-resident. Cross-CTA
// overlap fills the per-stage bubbles single-CTA scheduling couldn't.
// Price: x read twice (DRAM 25%->~50%).

static constexpr int DIM_S = 1024;
static constexpr int DIM_V = 8192;
static constexpr int DIM_D = 256;

static constexpr int TM     = 64;           // CTA M tile
static constexpr int TN     = 128;          // CTA N tile (half of D)
static constexpr int TKB    = 64;           // K per stage
static constexpr int NSTAGE = DIM_V / TKB;  // 128
static constexpr int RING   = 4;

static constexpr uint32_t A_BYTES  = TM * TKB * 2;        // 8 KB
static constexpr uint32_t B_BYTES  = TN * TKB * 2;        // 16 KB
static constexpr uint32_t ST_BYTES = A_BYTES + B_BYTES;   // 24 KB
static constexpr uint32_t SMEM_DYN = RING * ST_BYTES + 1024;  // ~97 KB

// Transposed fp16 table: [d][v], value = fp16(emb[v][d] * 16). 4 MB.
__device__ __align__(128) unsigned short g_embT[(size_t)DIM_D * DIM_V];

__device__ __forceinline__ uint32_t smem_u32(const void* p) {
    return (uint32_t)__cvta_generic_to_shared(p);
}
__device__ __forceinline__ uint32_t sw128(uint32_t off) {
    return off ^ ((off >> 3) & 0x70u);
}

// ---------------------------------------------------------------------------
// Prep: transpose + fp16(emb*16)
// ---------------------------------------------------------------------------
__global__ void prep_transpose(const float* __restrict__ emb) {
    __shared__ float tile[32][33];
    const int v0 = blockIdx.x * 32, d0 = blockIdx.y * 32, t = threadIdx.x;
#pragma unroll
    for (int it = 0; it < 4; ++it) {
        int idx = t + it * 256, i = idx >> 5, j = idx & 31;
        tile[i][j] = emb[(size_t)(v0 + i) * DIM_D + d0 + j];
    }
    __syncthreads();
#pragma unroll
    for (int it = 0; it < 2; ++it) {
        int idx = t + it * 256, dl = idx >> 4, vp = idx & 15;
        __half2 h = __floats2half2_rn(tile[vp * 2][dl] * 16.0f,
                                      tile[vp * 2 + 1][dl] * 16.0f);
        *reinterpret_cast<__half2*>(
            &g_embT[(size_t)(d0 + dl) * DIM_V + v0 + vp * 2]) = h;
    }
}

// ---------------------------------------------------------------------------
// Producers (256 threads). Stage = 64 K-cols.
// A: thread owns 16 ints of row t>>2 (chunk q=t&3); bit-trick x->fp16.
// ---------------------------------------------------------------------------
__device__ __forceinline__ void load_conv_a(uint32_t* vap, int& any,
                                            const int* __restrict__ x,
                                            int m0, int stage, int t) {
    const int4* xr = reinterpret_cast<const int4*>(x);
    int row = t >> 2, q = t & 3;
    size_t o = (size_t)(m0 + row) * (DIM_V / 4) + (size_t)stage * 16 + q * 4;
    any = 0;
#pragma unroll
    for (int j = 0; j < 4; ++j) {
        int4 v = xr[o + j];
        any |= v.x | v.y | v.z | v.w;
        vap[2 * j + 0] = (uint32_t)v.x * 0x3C00u + (uint32_t)v.y * 0x3C000000u;
        vap[2 * j + 1] = (uint32_t)v.z * 0x3C00u + (uint32_t)v.w * 0x3C000000u;
    }
}

__device__ __forceinline__ void store_a(const uint32_t* vap, int any,
                                        uint32_t abase, int t, int* flags) {
    int row = t >> 2, q = t & 3;
    if (any) flags[row] = 1;                 // benign same-value race
#pragma unroll
    for (int s = 0; s < 2; ++s) {
        uint32_t dst = abase + sw128((uint32_t)row * 128u +
                                     (uint32_t)q * 32u + (uint32_t)s * 16u);
        asm volatile("st.shared.v4.b32 [%0], {%1,%2,%3,%4};"
                     :: "r"(dst), "r"(vap[s * 4 + 0]), "r"(vap[s * 4 + 1]),
                        "r"(vap[s * 4 + 2]), "r"(vap[s * 4 + 3]));
    }
}

__device__ __forceinline__ void issue_b(uint32_t bbase, int d0, int stage, int t) {
    const char* bsrc = reinterpret_cast<const char*>(g_embT);
#pragma unroll
    for (int i = 0; i < 4; ++i) {
        int idx = t + i * 256;
        int row = idx >> 3, seg = idx & 7;   // 128 rows x 8 x 16B
        uint32_t dst = bbase + sw128((uint32_t)row * 128u + (uint32_t)seg * 16u);
        const void* src = bsrc + (size_t)(d0 + row) * (DIM_V * 2)
                               + (size_t)stage * 128 + seg * 16;
        asm volatile("cp.async.cg.shared.global [%0], [%1], 16;"
                     :: "r"(dst), "l"(src));
    }
}

// ---------------------------------------------------------------------------
// GEMM: grid 256 = 128 M-tiles x 2 N-halves; 256 thr; 8 warps 2Mx4N;
// warp 32x32; 2 CTAs/SM.
// ---------------------------------------------------------------------------
__global__ __launch_bounds__(256, 2)
void multihot_gemm(const int* __restrict__ x, const float* __restrict__ pos,
                   float* __restrict__ out) {
    extern __shared__ char dynsm[];
    __shared__ int flags[TM];

    const int t = threadIdx.x;
    const int wid = t >> 5, lane = t & 31;
    const int wm = wid & 1, wn = wid >> 1;   // wm 0..1 (M), wn 0..3 (N)
    const int m0 = (blockIdx.x & 127) * TM;
    const int d0 = (blockIdx.x >> 7) * TN;   // N half

    const uint32_t base = (smem_u32(dynsm) + 1023u) & ~1023u;

    for (int i = t; i < TM; i += 256) flags[i] = 0;
    __syncthreads();

    float acc[2][4][4];
#pragma unroll
    for (int a = 0; a < 2; ++a)
#pragma unroll
        for (int b = 0; b < 4; ++b)
#pragma unroll
            for (int c = 0; c < 4; ++c) acc[a][b][c] = 0.0f;

    // per-lane ldmatrix addresses (128B rows; swizzle xor = (lane&7)<<4)
    const uint32_t a_khalf = (uint32_t)(lane >> 4) << 4;
    const uint32_t a_rxor  = (uint32_t)(lane & 7) << 4;
    uint32_t a_row[2];
#pragma unroll
    for (int mt = 0; mt < 2; ++mt)
        a_row[mt] = (uint32_t)(wm * 32 + mt * 16 + (lane & 15)) * 128u;

    const uint32_t b_khalf = (uint32_t)((lane >> 3) & 1) << 4;
    uint32_t b_row[2], b_rxor[2];
#pragma unroll
    for (int ntp = 0; ntp < 2; ++ntp) {
        int nrow = wn * 32 + ntp * 16 + (lane & 7) + ((lane >> 4) << 3);
        b_row[ntp]  = (uint32_t)nrow * 128u;
        b_rxor[ntp] = (uint32_t)(nrow & 7) << 4;
    }

    // prologue: produce stages 0..2; prefetch A of stage 3 to regs
    uint32_t vap[8];
    int any;
    load_conv_a(vap, any, x, m0, 0, t);
#pragma unroll
    for (int s = 0; s < RING - 1; ++s) {
        uint32_t sb = base + (uint32_t)s * ST_BYTES;
        store_a(vap, any, sb, t, flags);
        issue_b(sb + A_BYTES, d0, s, t);
        asm volatile("cp.async.commit_group;" ::: "memory");
        load_conv_a(vap, any, x, m0, s + 1, t);
    }

#define LOAD_FRAGS(AF, BF, AB, BB, KS)                                         \
    do {                                                                       \
        const uint32_t kb = (uint32_t)(KS) * 32u;                              \
        _Pragma("unroll")                                                      \
        for (int mt = 0; mt < 2; ++mt) {                                       \
            uint32_t addr = (AB) + a_row[mt] + ((kb + a_khalf) ^ a_rxor);      \
            asm volatile("ldmatrix.sync.aligned.m8n8.x4.shared.b16 "           \
                         "{%0,%1,%2,%3}, [%4];"                                \
                         : "=r"((AF)[mt][0]), "=r"((AF)[mt][1]),               \
                           "=r"((AF)[mt][2]), "=r"((AF)[mt][3])                \
                         : "r"(addr));                                         \
        }                                                                      \
        _Pragma("unroll")                                                      \
        for (int ntp = 0; ntp < 2; ++ntp) {                                    \
            uint32_t addr = (BB) + b_row[ntp] + ((kb + b_khalf) ^ b_rxor[ntp]);\
            asm volatile("ldmatrix.sync.aligned.m8n8.x4.shared.b16 "           \
                         "{%0,%1,%2,%3}, [%4];"                                \
                         : "=r"((BF)[ntp][0]), "=r"((BF)[ntp][1]),             \
                           "=r"((BF)[ntp][2]), "=r"((BF)[ntp][3])              \
                         : "r"(addr));                                         \
        }                                                                      \
    } while (0)

#define MMA_SET(AF, BF)                                                        \
    do {                                                                       \
        _Pragma("unroll")                                                      \
        for (int mt = 0; mt < 2; ++mt) {                                       \
            _Pragma("unroll")                                                  \
            for (int nt = 0; nt < 4; ++nt) {                                   \
                float* c = acc[mt][nt];                                        \
                const uint32_t* bp = &(BF)[nt >> 1][(nt & 1) * 2];             \
                asm("mma.sync.aligned.m16n8k16.row.col.f32.f16.f16.f32 "       \
                    "{%0,%1,%2,%3}, {%4,%5,%6,%7}, {%8,%9}, {%0,%1,%2,%3};"    \
                    : "+f"(c[0]), "+f"(c[1]), "+f"(c[2]), "+f"(c[3])           \
                    : "r"((AF)[mt][0]), "r"((AF)[mt][1]),                      \
                      "r"((AF)[mt][2]), "r"((AF)[mt][3]),                      \
                      "r"(bp[0]), "r"(bp[1]));                                 \
            }                                                                  \
        }                                                                      \
    } while (0)

    uint32_t af0[2][4], bf0[2][4], af1[2][4], bf1[2][4];

    // mainloop (R9 structure verbatim)
#pragma unroll 1
    for (int k = 0; k < NSTAGE; ++k) {
        asm volatile("cp.async.wait_group 1;" ::: "memory");
        __syncthreads();

        const uint32_t soff = (uint32_t)(k & (RING - 1)) * ST_BYTES;
        const uint32_t ab = base + soff;
        const uint32_t bb = base + soff + A_BYTES;

        // ks0 fragments early: LDSM latency overlaps producer work
        LOAD_FRAGS(af0, bf0, ab, bb, 0);

        if (k + RING - 1 < NSTAGE) {
            uint32_t sb = base + (uint32_t)((k + RING - 1) & (RING - 1)) * ST_BYTES;
            store_a(vap, any, sb, t, flags);
            issue_b(sb + A_BYTES, d0, k + RING - 1, t);
        }
        asm volatile("cp.async.commit_group;" ::: "memory");
        if (k + RING < NSTAGE) load_conv_a(vap, any, x, m0, k + RING, t);

        LOAD_FRAGS(af1, bf1, ab, bb, 1);
        MMA_SET(af0, bf0);
        LOAD_FRAGS(af0, bf0, ab, bb, 2);
        MMA_SET(af1, bf1);
        LOAD_FRAGS(af1, bf1, ab, bb, 3);
        MMA_SET(af0, bf0);
        MMA_SET(af1, bf1);
    }

    __syncthreads();   // flags fully written

    // fused epilogue: out = acc + pos*any_tok  (x16 folded into table)
#pragma unroll
    for (int mt = 0; mt < 2; ++mt) {
#pragma unroll
        for (int half = 0; half < 2; ++half) {
            const int rl = wm * 32 + mt * 16 + (lane >> 2) + half * 8;
            const int grow = m0 + rl;
            const float tokf = flags[rl] ? 1.0f : 0.0f;
            const float* prow = pos + (size_t)(grow & (DIM_S - 1)) * DIM_D;
            float* orow = out + (size_t)grow * DIM_D;
#pragma unroll
            for (int nt = 0; nt < 4; ++nt) {
                const int col = d0 + wn * 32 + nt * 8 + (lane & 3) * 2;
                float2 pv = *reinterpret_cast<const float2*>(prow + col);
                float2 ov;
                ov.x = acc[mt][nt][half * 2 + 0] + pv.x * tokf;
                ov.y = acc[mt][nt][half * 2 + 1] + pv.y * tokf;
                *reinterpret_cast<float2*>(orow + col) = ov;
            }
        }
    }
}

// ---------------------------------------------------------------------------
extern "C" void kernel_launch(void* const* d_in, const int* in_sizes, int n_in,
                              void* d_out, int out_size) {
    (void)in_sizes; (void)n_in; (void)out_size;
    const int*   x   = (const int*)d_in[0];     // [8,1024,8192] int32 (0/1)
    const float* emb = (const float*)d_in[1];   // [8192,256] f32
    const float* pos = (const float*)d_in[2];   // [1,1024,256] f32
    float* out = (float*)d_out;                 // [8,1024,256] f32

    cudaFuncSetAttribute(multihot_gemm,
                         cudaFuncAttributeMaxDynamicSharedMemorySize, SMEM_DYN);

    prep_transpose<<<dim3(DIM_V / 32, DIM_D / 32), 256>>>(emb);
    multihot_gemm<<<256, 256, SMEM_DYN>>>(x, pos, out);
}

// round 16
// speedup vs baseline: 1.1312x; 1.1312x over previous
#include <cuda_runtime.h>
#include <cuda_fp16.h>
#include <cstdint>
#include <cstddef>

// out[b,s,d] = 16*sum_v x[b,s,v]*emb[v,d] + pos[s,d]*any(x[b,s,:])
// GEMM M=8192, N=256, K=8192. fp16 table = fp16(emb*16), x exact in fp16,
// fp32 accumulate. Baseline PTX path (compute_103: no tcgen05).
// R16 = R9 restored byte-for-byte (best known: 512 thr, 16 warps 2Mx8N,
// warp 32x32, RING=4, wait_group 2, frag dbl-buffer) + ONE delta:
// bit-trick x->fp16 producer (x in {0,1}: pk = v0*0x3C00 + v1*0x3C000000).

static constexpr int DIM_S = 1024;
static constexpr int DIM_V = 8192;
static constexpr int DIM_D = 256;

static constexpr int TM     = 64;           // CTA M tile
static constexpr int TKB    = 64;           // K per stage
static constexpr int NSTAGE = DIM_V / TKB;  // 128
static constexpr int RING   = 4;

static constexpr uint32_t A_BYTES  = TM * TKB * 2;        // 8 KB
static constexpr uint32_t B_BYTES  = DIM_D * TKB * 2;     // 32 KB
static constexpr uint32_t ST_BYTES = A_BYTES + B_BYTES;   // 40 KB
static constexpr uint32_t SMEM_DYN = RING * ST_BYTES + 1024;

// Transposed fp16 table: [d][v], value = fp16(emb[v][d] * 16). 4 MB.
__device__ __align__(128) unsigned short g_embT[(size_t)DIM_D * DIM_V];

__device__ __forceinline__ uint32_t smem_u32(const void* p) {
    return (uint32_t)__cvta_generic_to_shared(p);
}
__device__ __forceinline__ uint32_t sw128(uint32_t off) {
    return off ^ ((off >> 3) & 0x70u);
}

// ---------------------------------------------------------------------------
// Prep: transpose + fp16(emb*16)
// ---------------------------------------------------------------------------
__global__ void prep_transpose(const float* __restrict__ emb) {
    __shared__ float tile[32][33];
    const int v0 = blockIdx.x * 32, d0 = blockIdx.y * 32, t = threadIdx.x;
#pragma unroll
    for (int it = 0; it < 4; ++it) {
        int idx = t + it * 256, i = idx >> 5, j = idx & 31;
        tile[i][j] = emb[(size_t)(v0 + i) * DIM_D + d0 + j];
    }
    __syncthreads();
#pragma unroll
    for (int it = 0; it < 2; ++it) {
        int idx = t + it * 256, dl = idx >> 4, vp = idx & 15;
        __half2 h = __floats2half2_rn(tile[vp * 2][dl] * 16.0f,
                                      tile[vp * 2 + 1][dl] * 16.0f);
        *reinterpret_cast<__half2*>(
            &g_embT[(size_t)(d0 + dl) * DIM_V + v0 + vp * 2]) = h;
    }
}

// ---------------------------------------------------------------------------
// Producers (512 threads). A: thread owns 8 ints of row t>>3 (chunk q=t&7);
// converted to 4 packed fp16x2 at load (x in {0,1}: exact bit trick).
// ---------------------------------------------------------------------------
__device__ __forceinline__ void load_conv_a(uint32_t* vap, int& any,
                                            const int* __restrict__ x,
                                            int m0, int stage, int t) {
    const int4* xr = reinterpret_cast<const int4*>(x);
    int row = t >> 3, q = t & 7;
    size_t o = (size_t)(m0 + row) * (DIM_V / 4) + (size_t)stage * 16 + q * 2;
    int4 v0 = xr[o];
    int4 v1 = xr[o + 1];
    any = v0.x | v0.y | v0.z | v0.w | v1.x | v1.y | v1.z | v1.w;
    vap[0] = (uint32_t)v0.x * 0x3C00u + (uint32_t)v0.y * 0x3C000000u;
    vap[1] = (uint32_t)v0.z * 0x3C00u + (uint32_t)v0.w * 0x3C000000u;
    vap[2] = (uint32_t)v1.x * 0x3C00u + (uint32_t)v1.y * 0x3C000000u;
    vap[3] = (uint32_t)v1.z * 0x3C00u + (uint32_t)v1.w * 0x3C000000u;
}

__device__ __forceinline__ void store_a(const uint32_t* vap, int any,
                                        uint32_t abase, int t, int* flags) {
    int row = t >> 3, q = t & 7;
    if (any) flags[row] = 1;                 // benign same-value race
    uint32_t dst = abase + sw128((uint32_t)row * 128u + (uint32_t)q * 16u);
    asm volatile("st.shared.v4.b32 [%0], {%1,%2,%3,%4};"
                 :: "r"(dst), "r"(vap[0]), "r"(vap[1]),
                    "r"(vap[2]), "r"(vap[3]));
}

__device__ __forceinline__ void issue_b(uint32_t bbase, int stage, int t) {
    const char* bsrc = reinterpret_cast<const char*>(g_embT);
#pragma unroll
    for (int i = 0; i < 4; ++i) {
        int idx = t + i * 512;
        int row = idx >> 3, seg = idx & 7;   // 256 rows x 8 x 16B
        uint32_t dst = bbase + sw128((uint32_t)row * 128u + (uint32_t)seg * 16u);
        const void* src = bsrc + (size_t)row * (DIM_V * 2)
                               + (size_t)stage * 128 + seg * 16;
        asm volatile("cp.async.cg.shared.global [%0], [%1], 16;"
                     :: "r"(dst), "l"(src));
    }
}

// ---------------------------------------------------------------------------
// GEMM: 128 CTAs x 512 thr; CTA 64x256; 16 warps 2Mx8N; warp 32x32.
// ---------------------------------------------------------------------------
__global__ __launch_bounds__(512, 1)
void multihot_gemm(const int* __restrict__ x, const float* __restrict__ pos,
                   float* __restrict__ out) {
    extern __shared__ char dynsm[];
    __shared__ int flags[TM];

    const int t = threadIdx.x;
    const int wid = t >> 5, lane = t & 31;
    const int wm = wid & 1, wn = wid >> 1;   // wm 0..1 (M), wn 0..7 (N)
    const int m0 = blockIdx.x * TM;

    const uint32_t base = (smem_u32(dynsm) + 1023u) & ~1023u;

    for (int i = t; i < TM; i += 512) flags[i] = 0;
    __syncthreads();

    float acc[2][4][4];
#pragma unroll
    for (int a = 0; a < 2; ++a)
#pragma unroll
        for (int b = 0; b < 4; ++b)
#pragma unroll
            for (int c = 0; c < 4; ++c) acc[a][b][c] = 0.0f;

    // prologue: produce stages 0..2; prefetch A of stage 3 to regs
    uint32_t vap[4];
    int any;
    load_conv_a(vap, any, x, m0, 0, t);
#pragma unroll
    for (int s = 0; s < RING - 1; ++s) {
        uint32_t sb = base + (uint32_t)s * ST_BYTES;
        store_a(vap, any, sb, t, flags);
        issue_b(sb + A_BYTES, s, t);
        asm volatile("cp.async.commit_group;" ::: "memory");
        load_conv_a(vap, any, x, m0, s + 1, t);
    }
    // vap holds A(stage 3)

    // per-lane ldmatrix addresses (128B rows; swizzle xor = (lane&7)<<4)
    const uint32_t a_khalf = (uint32_t)(lane >> 4) << 4;
    const uint32_t a_rxor  = (uint32_t)(lane & 7) << 4;
    uint32_t a_row[2];
#pragma unroll
    for (int mt = 0; mt < 2; ++mt)
        a_row[mt] = (uint32_t)(wm * 32 + mt * 16 + (lane & 15)) * 128u;

    const uint32_t b_khalf = (uint32_t)((lane >> 3) & 1) << 4;
    uint32_t b_row[2], b_rxor[2];
#pragma unroll
    for (int ntp = 0; ntp < 2; ++ntp) {
        int nrow = wn * 32 + ntp * 16 + (lane & 7) + ((lane >> 4) << 3);
        b_row[ntp]  = (uint32_t)nrow * 128u;
        b_rxor[ntp] = (uint32_t)(nrow & 7) << 4;
    }

#define LOAD_FRAGS(AF, BF, AB, BB, KS)                                         \
    do {                                                                       \
        const uint32_t kb = (uint32_t)(KS) * 32u;                              \
        _Pragma("unroll")                                                      \
        for (int mt = 0; mt < 2; ++mt) {                                       \
            uint32_t addr = (AB) + a_row[mt] + ((kb + a_khalf) ^ a_rxor);      \
            asm volatile("ldmatrix.sync.aligned.m8n8.x4.shared.b16 "           \
                         "{%0,%1,%2,%3}, [%4];"                                \
                         : "=r"((AF)[mt][0]), "=r"((AF)[mt][1]),               \
                           "=r"((AF)[mt][2]), "=r"((AF)[mt][3])                \
                         : "r"(addr));                                         \
        }                                                                      \
        _Pragma("unroll")                                                      \
        for (int ntp = 0; ntp < 2; ++ntp) {                                    \
            uint32_t addr = (BB) + b_row[ntp] + ((kb + b_khalf) ^ b_rxor[ntp]);\
            asm volatile("ldmatrix.sync.aligned.m8n8.x4.shared.b16 "           \
                         "{%0,%1,%2,%3}, [%4];"                                \
                         : "=r"((BF)[ntp][0]), "=r"((BF)[ntp][1]),             \
                           "=r"((BF)[ntp][2]), "=r"((BF)[ntp][3])              \
                         : "r"(addr));                                         \
        }                                                                      \
    } while (0)

#define MMA_SET(AF, BF)                                                        \
    do {                                                                       \
        _Pragma("unroll")                                                      \
        for (int mt = 0; mt < 2; ++mt) {                                       \
            _Pragma("unroll")                                                  \
            for (int nt = 0; nt < 4; ++nt) {                                   \
                float* c = acc[mt][nt];                                        \
                const uint32_t* bp = &(BF)[nt >> 1][(nt & 1) * 2];             \
                asm("mma.sync.aligned.m16n8k16.row.col.f32.f16.f16.f32 "       \
                    "{%0,%1,%2,%3}, {%4,%5,%6,%7}, {%8,%9}, {%0,%1,%2,%3};"    \
                    : "+f"(c[0]), "+f"(c[1]), "+f"(c[2]), "+f"(c[3])           \
                    : "r"((AF)[mt][0]), "r"((AF)[mt][1]),                      \
                      "r"((AF)[mt][2]), "r"((AF)[mt][3]),                      \
                      "r"(bp[0]), "r"(bp[1]));                                 \
            }                                                                  \
        }                                                                      \
    } while (0)

    uint32_t af0[2][4], bf0[2][4], af1[2][4], bf1[2][4];

    // mainloop (R9 structure verbatim)
#pragma unroll 1
    for (int k = 0; k < NSTAGE; ++k) {
        asm volatile("cp.async.wait_group %0;" :: "n"(RING - 2) : "memory");
        __syncthreads();

        const uint32_t soff = (uint32_t)(k & (RING - 1)) * ST_BYTES;
        const uint32_t ab = base + soff;
        const uint32_t bb = base + soff + A_BYTES;

        // start ks0 fragment loads early: latency overlaps producer work
        LOAD_FRAGS(af0, bf0, ab, bb, 0);

        if (k + RING - 1 < NSTAGE) {
            uint32_t sb = base + (uint32_t)((k + RING - 1) & (RING - 1)) * ST_BYTES;
            store_a(vap, any, sb, t, flags);
            issue_b(sb + A_BYTES, k + RING - 1, t);
        }
        if (k + RING < NSTAGE) load_conv_a(vap, any, x, m0, k + RING, t);
        asm volatile("cp.async.commit_group;" ::: "memory");

        // ks-pipelined: load ks+1 while issuing MMAs of ks
        LOAD_FRAGS(af1, bf1, ab, bb, 1);
        MMA_SET(af0, bf0);
        LOAD_FRAGS(af0, bf0, ab, bb, 2);
        MMA_SET(af1, bf1);
        LOAD_FRAGS(af1, bf1, ab, bb, 3);
        MMA_SET(af0, bf0);
        MMA_SET(af1, bf1);
    }

    __syncthreads();   // flags fully written

    // fused epilogue: out = acc + pos*any_tok  (x16 folded into table)
#pragma unroll
    for (int mt = 0; mt < 2; ++mt) {
#pragma unroll
        for (int half = 0; half < 2; ++half) {
            const int rl = wm * 32 + mt * 16 + (lane >> 2) + half * 8;
            const int grow = m0 + rl;
            const float tokf = flags[rl] ? 1.0f : 0.0f;
            const float* prow = pos + (size_t)(grow & (DIM_S - 1)) * DIM_D;
            float* orow = out + (size_t)grow * DIM_D;
#pragma unroll
            for (int nt = 0; nt < 4; ++nt) {
                const int col = wn * 32 + nt * 8 + (lane & 3) * 2;
                float2 pv = *reinterpret_cast<const float2*>(prow + col);
                float2 ov;
                ov.x = acc[mt][nt][half * 2 + 0] + pv.x * tokf;
                ov.y = acc[mt][nt][half * 2 + 1] + pv.y * tokf;
                *reinterpret_cast<float2*>(orow + col) = ov;
            }
        }
    }
}

// ---------------------------------------------------------------------------
extern "C" void kernel_launch(void* const* d_in, const int* in_sizes, int n_in,
                              void* d_out, int out_size) {
    (void)in_sizes; (void)n_in; (void)out_size;
    const int*   x   = (const int*)d_in[0];     // [8,1024,8192] int32 (0/1)
    const float* emb = (const float*)d_in[1];   // [8192,256] f32
    const float* pos = (const float*)d_in[2];   // [1,1024,256] f32
    float* out = (float*)d_out;                 // [8,1024,256] f32

    cudaFuncSetAttribute(multihot_gemm,
                         cudaFuncAttributeMaxDynamicSharedMemorySize, SMEM_DYN);

    prep_transpose<<<dim3(DIM_V / 32, DIM_D / 32), 256>>>(emb);
    multihot_gemm<<<(8 * DIM_S) / TM, 512, SMEM_DYN>>>(x, pos, out);
}

// round 17
// speedup vs baseline: 1.6952x; 1.4986x over previous
#include <cuda_runtime.h>
#include <cuda_fp16.h>
#include <cstdint>
#include <cstddef>

// out[b,s,d] = 16*sum_v x[b,s,v]*emb[v,d] + pos[s,d]*any(x[b,s,:])
// GEMM M=8192, N=256, K=8192. fp16 table = fp16(emb*16), x exact in fp16,
// fp32 accumulate. Baseline PTX path (compute_103: no tcgen05).
// R17 = R9 byte-for-byte (512 thr, 16 warps 2Mx8N, warp 32x32, RING=4,
// wait_group 2, frag dbl-buffer, DEFERRED x consumption: LDG in load_a,
// conversion one stage later in store_a) with the conversion itself done
// by the exact IMAD bit trick instead of I2F/F2F.

static constexpr int DIM_S = 1024;
static constexpr int DIM_V = 8192;
static constexpr int DIM_D = 256;

static constexpr int TM     = 64;           // CTA M tile
static constexpr int TKB    = 64;           // K per stage
static constexpr int NSTAGE = DIM_V / TKB;  // 128
static constexpr int RING   = 4;

static constexpr uint32_t A_BYTES  = TM * TKB * 2;        // 8 KB
static constexpr uint32_t B_BYTES  = DIM_D * TKB * 2;     // 32 KB
static constexpr uint32_t ST_BYTES = A_BYTES + B_BYTES;   // 40 KB
static constexpr uint32_t SMEM_DYN = RING * ST_BYTES + 1024;

// Transposed fp16 table: [d][v], value = fp16(emb[v][d] * 16). 4 MB.
__device__ __align__(128) unsigned short g_embT[(size_t)DIM_D * DIM_V];

__device__ __forceinline__ uint32_t smem_u32(const void* p) {
    return (uint32_t)__cvta_generic_to_shared(p);
}
__device__ __forceinline__ uint32_t sw128(uint32_t off) {
    return off ^ ((off >> 3) & 0x70u);
}

// ---------------------------------------------------------------------------
// Prep: transpose + fp16(emb*16)
// ---------------------------------------------------------------------------
__global__ void prep_transpose(const float* __restrict__ emb) {
    __shared__ float tile[32][33];
    const int v0 = blockIdx.x * 32, d0 = blockIdx.y * 32, t = threadIdx.x;
#pragma unroll
    for (int it = 0; it < 4; ++it) {
        int idx = t + it * 256, i = idx >> 5, j = idx & 31;
        tile[i][j] = emb[(size_t)(v0 + i) * DIM_D + d0 + j];
    }
    __syncthreads();
#pragma unroll
    for (int it = 0; it < 2; ++it) {
        int idx = t + it * 256, dl = idx >> 4, vp = idx & 15;
        __half2 h = __floats2half2_rn(tile[vp * 2][dl] * 16.0f,
                                      tile[vp * 2 + 1][dl] * 16.0f);
        *reinterpret_cast<__half2*>(
            &g_embT[(size_t)(d0 + dl) * DIM_V + v0 + vp * 2]) = h;
    }
}

// ---------------------------------------------------------------------------
// Producers (512 threads).
// load_a: ONLY issues the x LDGs (values consumed a full stage later).
// store_a: consumes them (bit-trick x->fp16; exact for x in {0,1}).
// ---------------------------------------------------------------------------
__device__ __forceinline__ void load_a(int4* va, const int* __restrict__ x,
                                       int m0, int stage, int t) {
    const int4* xr = reinterpret_cast<const int4*>(x);
    int row = t >> 3, q = t & 7;
    size_t o = (size_t)(m0 + row) * (DIM_V / 4) + (size_t)stage * 16 + q * 2;
    va[0] = xr[o];
    va[1] = xr[o + 1];
}

__device__ __forceinline__ void store_a(const int4* va, uint32_t abase,
                                        int t, int* flags) {
    int row = t >> 3, q = t & 7;
    int4 v0 = va[0], v1 = va[1];
    int any = v0.x | v0.y | v0.z | v0.w | v1.x | v1.y | v1.z | v1.w;
    if (any) flags[row] = 1;                 // benign same-value race
    uint32_t p0 = (uint32_t)v0.x * 0x3C00u + (uint32_t)v0.y * 0x3C000000u;
    uint32_t p1 = (uint32_t)v0.z * 0x3C00u + (uint32_t)v0.w * 0x3C000000u;
    uint32_t p2 = (uint32_t)v1.x * 0x3C00u + (uint32_t)v1.y * 0x3C000000u;
    uint32_t p3 = (uint32_t)v1.z * 0x3C00u + (uint32_t)v1.w * 0x3C000000u;
    uint32_t dst = abase + sw128((uint32_t)row * 128u + (uint32_t)q * 16u);
    asm volatile("st.shared.v4.b32 [%0], {%1,%2,%3,%4};"
                 :: "r"(dst), "r"(p0), "r"(p1), "r"(p2), "r"(p3));
}

__device__ __forceinline__ void issue_b(uint32_t bbase, int stage, int t) {
    const char* bsrc = reinterpret_cast<const char*>(g_embT);
#pragma unroll
    for (int i = 0; i < 4; ++i) {
        int idx = t + i * 512;
        int row = idx >> 3, seg = idx & 7;   // 256 rows x 8 x 16B
        uint32_t dst = bbase + sw128((uint32_t)row * 128u + (uint32_t)seg * 16u);
        const void* src = bsrc + (size_t)row * (DIM_V * 2)
                               + (size_t)stage * 128 + seg * 16;
        asm volatile("cp.async.cg.shared.global [%0], [%1], 16;"
                     :: "r"(dst), "l"(src));
    }
}

// ---------------------------------------------------------------------------
// GEMM: 128 CTAs x 512 thr; CTA 64x256; 16 warps 2Mx8N; warp 32x32.
// ---------------------------------------------------------------------------
__global__ __launch_bounds__(512, 1)
void multihot_gemm(const int* __restrict__ x, const float* __restrict__ pos,
                   float* __restrict__ out) {
    extern __shared__ char dynsm[];
    __shared__ int flags[TM];

    const int t = threadIdx.x;
    const int wid = t >> 5, lane = t & 31;
    const int wm = wid & 1, wn = wid >> 1;   // wm 0..1 (M), wn 0..7 (N)
    const int m0 = blockIdx.x * TM;

    const uint32_t base = (smem_u32(dynsm) + 1023u) & ~1023u;

    for (int i = t; i < TM; i += 512) flags[i] = 0;
    __syncthreads();

    float acc[2][4][4];
#pragma unroll
    for (int a = 0; a < 2; ++a)
#pragma unroll
        for (int b = 0; b < 4; ++b)
#pragma unroll
            for (int c = 0; c < 4; ++c) acc[a][b][c] = 0.0f;

    // prologue: produce stages 0..2; x loads for stage 3 in flight
    int4 va[2];
    load_a(va, x, m0, 0, t);
#pragma unroll
    for (int s = 0; s < RING - 1; ++s) {
        uint32_t sb = base + (uint32_t)s * ST_BYTES;
        store_a(va, sb, t, flags);
        issue_b(sb + A_BYTES, s, t);
        asm volatile("cp.async.commit_group;" ::: "memory");
        load_a(va, x, m0, s + 1, t);
    }
    // va holds A(stage 3)

    // per-lane ldmatrix addresses (128B rows; swizzle xor = (lane&7)<<4)
    const uint32_t a_khalf = (uint32_t)(lane >> 4) << 4;
    const uint32_t a_rxor  = (uint32_t)(lane & 7) << 4;
    uint32_t a_row[2];
#pragma unroll
    for (int mt = 0; mt < 2; ++mt)
        a_row[mt] = (uint32_t)(wm * 32 + mt * 16 + (lane & 15)) * 128u;

    const uint32_t b_khalf = (uint32_t)((lane >> 3) & 1) << 4;
    uint32_t b_row[2], b_rxor[2];
#pragma unroll
    for (int ntp = 0; ntp < 2; ++ntp) {
        int nrow = wn * 32 + ntp * 16 + (lane & 7) + ((lane >> 4) << 3);
        b_row[ntp]  = (uint32_t)nrow * 128u;
        b_rxor[ntp] = (uint32_t)(nrow & 7) << 4;
    }

#define LOAD_FRAGS(AF, BF, AB, BB, KS)                                         \
    do {                                                                       \
        const uint32_t kb = (uint32_t)(KS) * 32u;                              \
        _Pragma("unroll")                                                      \
        for (int mt = 0; mt < 2; ++mt) {                                       \
            uint32_t addr = (AB) + a_row[mt] + ((kb + a_khalf) ^ a_rxor);      \
            asm volatile("ldmatrix.sync.aligned.m8n8.x4.shared.b16 "           \
                         "{%0,%1,%2,%3}, [%4];"                                \
                         : "=r"((AF)[mt][0]), "=r"((AF)[mt][1]),               \
                           "=r"((AF)[mt][2]), "=r"((AF)[mt][3])                \
                         : "r"(addr));                                         \
        }                                                                      \
        _Pragma("unroll")                                                      \
        for (int ntp = 0; ntp < 2; ++ntp) {                                    \
            uint32_t addr = (BB) + b_row[ntp] + ((kb + b_khalf) ^ b_rxor[ntp]);\
            asm volatile("ldmatrix.sync.aligned.m8n8.x4.shared.b16 "           \
                         "{%0,%1,%2,%3}, [%4];"                                \
                         : "=r"((BF)[ntp][0]), "=r"((BF)[ntp][1]),             \
                           "=r"((BF)[ntp][2]), "=r"((BF)[ntp][3])              \
                         : "r"(addr));                                         \
        }                                                                      \
    } while (0)

#define MMA_SET(AF, BF)                                                        \
    do {                                                                       \
        _Pragma("unroll")                                                      \
        for (int mt = 0; mt < 2; ++mt) {                                       \
            _Pragma("unroll")                                                  \
            for (int nt = 0; nt < 4; ++nt) {                                   \
                float* c = acc[mt][nt];                                        \
                const uint32_t* bp = &(BF)[nt >> 1][(nt & 1) * 2];             \
                asm("mma.sync.aligned.m16n8k16.row.col.f32.f16.f16.f32 "       \
                    "{%0,%1,%2,%3}, {%4,%5,%6,%7}, {%8,%9}, {%0,%1,%2,%3};"    \
                    : "+f"(c[0]), "+f"(c[1]), "+f"(c[2]), "+f"(c[3])           \
                    : "r"((AF)[mt][0]), "r"((AF)[mt][1]),                      \
                      "r"((AF)[mt][2]), "r"((AF)[mt][3]),                      \
                      "r"(bp[0]), "r"(bp[1]));                                 \
            }                                                                  \
        }                                                                      \
    } while (0)

    uint32_t af0[2][4], bf0[2][4], af1[2][4], bf1[2][4];

    // mainloop (R9 structure verbatim)
#pragma unroll 1
    for (int k = 0; k < NSTAGE; ++k) {
        asm volatile("cp.async.wait_group %0;" :: "n"(RING - 2) : "memory");
        __syncthreads();

        const uint32_t soff = (uint32_t)(k & (RING - 1)) * ST_BYTES;
        const uint32_t ab = base + soff;
        const uint32_t bb = base + soff + A_BYTES;

        // start ks0 fragment loads early: latency overlaps producer work
        LOAD_FRAGS(af0, bf0, ab, bb, 0);

        if (k + RING - 1 < NSTAGE) {
            uint32_t sb = base + (uint32_t)((k + RING - 1) & (RING - 1)) * ST_BYTES;
            store_a(va, sb, t, flags);
            issue_b(sb + A_BYTES, k + RING - 1, t);
        }
        if (k + RING < NSTAGE) load_a(va, x, m0, k + RING, t);
        asm volatile("cp.async.commit_group;" ::: "memory");

        // ks-pipelined: load ks+1 while issuing MMAs of ks
        LOAD_FRAGS(af1, bf1, ab, bb, 1);
        MMA_SET(af0, bf0);
        LOAD_FRAGS(af0, bf0, ab, bb, 2);
        MMA_SET(af1, bf1);
        LOAD_FRAGS(af1, bf1, ab, bb, 3);
        MMA_SET(af0, bf0);
        MMA_SET(af1, bf1);
    }

    __syncthreads();   // flags fully written

    // fused epilogue: out = acc + pos*any_tok  (x16 folded into table)
#pragma unroll
    for (int mt = 0; mt < 2; ++mt) {
#pragma unroll
        for (int half = 0; half < 2; ++half) {
            const int rl = wm * 32 + mt * 16 + (lane >> 2) + half * 8;
            const int grow = m0 + rl;
            const float tokf = flags[rl] ? 1.0f : 0.0f;
            const float* prow = pos + (size_t)(grow & (DIM_S - 1)) * DIM_D;
            float* orow = out + (size_t)grow * DIM_D;
#pragma unroll
            for (int nt = 0; nt < 4; ++nt) {
                const int col = wn * 32 + nt * 8 + (lane & 3) * 2;
                float2 pv = *reinterpret_cast<const float2*>(prow + col);
                float2 ov;
                ov.x = acc[mt][nt][half * 2 + 0] + pv.x * tokf;
                ov.y = acc[mt][nt][half * 2 + 1] + pv.y * tokf;
                *reinterpret_cast<float2*>(orow + col) = ov;
            }
        }
    }
}

// ---------------------------------------------------------------------------
extern "C" void kernel_launch(void* const* d_in, const int* in_sizes, int n_in,
                              void* d_out, int out_size) {
    (void)in_sizes; (void)n_in; (void)out_size;
    const int*   x   = (const int*)d_in[0];     // [8,1024,8192] int32 (0/1)
    const float* emb = (const float*)d_in[1];   // [8192,256] f32
    const float* pos = (const float*)d_in[2];   // [1,1024,256] f32
    float* out = (float*)d_out;                 // [8,1024,256] f32

    cudaFuncSetAttribute(multihot_gemm,
                         cudaFuncAttributeMaxDynamicSharedMemorySize, SMEM_DYN);

    prep_transpose<<<dim3(DIM_V / 32, DIM_D / 32), 256>>>(emb);
    multihot_gemm<<<(8 * DIM_S) / TM, 512, SMEM_DYN>>>(x, pos, out);
}